// round 2
// baseline (speedup 1.0000x reference)
#include <cuda_runtime.h>

// Problem constants (fixed shapes from the reference)
#define BB 2
#define FF 2
#define CC 64
#define HH 32
#define WW 104
#define DD 96
#define NPIX (HH * WW)          // 3328
#define EPSV 1e-7f

// Scratch (device globals; no allocation allowed)
__device__ float g_lkT[BB * FF * NPIX * CC];   // [B,F,H,W,C]  ~3.4 MB
__device__ float g_curT[BB * NPIX * CC];       // [B,H,W,C]    ~1.7 MB
__device__ float g_P[BB * FF * 12];            // (K @ pose)[:3,:4]
__device__ float g_valid[BB * FF];

// ---------------------------------------------------------------------------
// Setup: P = (K @ pose)[:3,:], valid = (sum(pose) != 0)
// ---------------------------------------------------------------------------
__global__ void setup_kernel(const float* __restrict__ K,
                             const float* __restrict__ poses) {
    int t = threadIdx.x;
    if (t >= BB * FF) return;
    int b = t / FF;
    const float* Kb = K + b * 16;
    const float* ps = poses + t * 16;
    float s = 0.f;
#pragma unroll
    for (int i = 0; i < 16; i++) s += ps[i];
    g_valid[t] = (s != 0.f) ? 1.f : 0.f;
#pragma unroll
    for (int i = 0; i < 3; i++)
#pragma unroll
        for (int j = 0; j < 4; j++) {
            float acc = 0.f;
#pragma unroll
            for (int k = 0; k < 4; k++) acc += Kb[i * 4 + k] * ps[k * 4 + j];
            g_P[t * 12 + i * 4 + j] = acc;
        }
}

// ---------------------------------------------------------------------------
// Transpose [nbf, C, NPIX] -> [nbf, NPIX, C] via shared tile (coalesced both
// sides). NPIX = 3328 is divisible by 32, so no bounds checks needed.
// ---------------------------------------------------------------------------
__global__ __launch_bounds__(256) void transpose_kernel(
    const float* __restrict__ in, float* __restrict__ out) {
    __shared__ float tile[CC][33];
    const int ntiles = NPIX / 32;  // 104
    int bf = blockIdx.x / ntiles;
    int p0 = (blockIdx.x % ntiles) * 32;
    int t = threadIdx.x;

    const float* inb = in + (size_t)bf * CC * NPIX;
    {
        int tx = t & 31, ty = t >> 5;  // ty: 0..7
#pragma unroll
        for (int c = ty; c < CC; c += 8)
            tile[c][tx] = inb[c * NPIX + p0 + tx];
    }
    __syncthreads();
    float* outb = out + (size_t)bf * NPIX * CC;
    {
        int wx = t & 63, wy = t >> 6;  // wy: 0..3
#pragma unroll
        for (int pl = wy; pl < 32; pl += 4)
            outb[(p0 + pl) * CC + wx] = tile[wx][pl];
    }
}

// ---------------------------------------------------------------------------
// Main cost kernel: one warp per (b,d,y,x). Lane l owns channels {2l, 2l+1}.
// ---------------------------------------------------------------------------
__global__ __launch_bounds__(256) void cost_kernel(
    const float* __restrict__ invK, const float* __restrict__ depth_bins,
    float* __restrict__ out) {
    int gtid = blockIdx.x * blockDim.x + threadIdx.x;
    int warp = gtid >> 5;
    int lane = gtid & 31;
    const int TOT = BB * DD * HH * WW;
    if (warp >= TOT) return;

    int x = warp % WW;
    int tmp = warp / WW;
    int y = tmp % HH;
    tmp /= HH;
    int d = tmp % DD;
    int b = tmp / DD;

    // interior mask: border of 2 pixels -> diffs are 0 for every f at every d,
    // so the whole D-column is 0 and the cmax fixup leaves it 0.
    if (y < 2 || y >= HH - 2 || x < 2 || x >= WW - 2) {
        if (lane == 0) out[warp] = 0.f;
        return;
    }

    const float* iv = invK + b * 16;
    float fx = (float)x, fy = (float)y;
    float camx = iv[0] * fx + iv[1] * fy + iv[2];
    float camy = iv[4] * fx + iv[5] * fy + iv[6];
    float camz = iv[8] * fx + iv[9] * fy + iv[10];
    float depth = depth_bins[d];

    const float2* cur2 =
        (const float2*)(g_curT + ((size_t)(b * HH + y) * WW + x) * CC);
    float2 cur = cur2[lane];

    float costsum = 0.f, counts = 0.f;
#pragma unroll
    for (int f = 0; f < FF; f++) {
        const float* P = g_P + (b * FF + f) * 12;
        float c0 = depth * (P[0] * camx + P[1] * camy + P[2] * camz) + P[3];
        float c1 = depth * (P[4] * camx + P[5] * camy + P[6] * camz) + P[7];
        float c2 = depth * (P[8] * camx + P[9] * camy + P[10] * camz) + P[11];
        float den = c2 + EPSV;
        float u = c0 / den;
        float v = c1 / den;

        float difff = 0.f;
        // warp-uniform branch
        if (u >= 2.f && u <= (float)(WW - 2) && v >= 2.f &&
            v <= (float)(HH - 2)) {
            float xf = floorf(u), yf = floorf(v);
            int xi = (int)xf, yi = (int)yf;
            float wx1 = u - xf, wy1 = v - yf;
            float wx0 = 1.f - wx1, wy0 = 1.f - wy1;
            float w00 = wy0 * wx0, w01 = wy0 * wx1;
            float w10 = wy1 * wx0, w11 = wy1 * wx1;

            // all 4 corners guaranteed in-bounds when edge mask passes
            const float* lk =
                g_lkT + ((size_t)((b * FF + f) * HH + yi) * WW + xi) * CC;
            const float2* r00 = (const float2*)lk;
            const float2* r01 = (const float2*)(lk + CC);
            const float2* r10 = (const float2*)(lk + WW * CC);
            const float2* r11 = (const float2*)(lk + WW * CC + CC);
            float2 v00 = r00[lane];
            float2 v01 = r01[lane];
            float2 v10 = r10[lane];
            float2 v11 = r11[lane];

            float sxv = w00 * v00.x + w01 * v01.x + w10 * v10.x + w11 * v11.x;
            float syv = w00 * v00.y + w01 * v01.y + w10 * v10.y + w11 * v11.y;
            float acc = fabsf(sxv - cur.x) + fabsf(syv - cur.y);
#pragma unroll
            for (int o = 16; o; o >>= 1)
                acc += __shfl_xor_sync(0xffffffffu, acc, o);
            difff = acc * (1.0f / CC);
        }
        difff *= g_valid[b * FF + f];
        costsum += difff;
        if (difff > 0.f) counts += 1.f;
    }
    if (lane == 0) out[warp] = costsum / (counts + EPSV);
}

// ---------------------------------------------------------------------------
// D-axis fixup: cost==0 -> max over D (computed on pre-fix values)
// ---------------------------------------------------------------------------
__global__ void fix_kernel(float* __restrict__ out) {
    int tid = blockIdx.x * blockDim.x + threadIdx.x;
    if (tid >= BB * HH * WW) return;
    int x = tid % WW;
    int y = (tid / WW) % HH;
    int b = tid / (WW * HH);
    float* base = out + ((size_t)b * DD * HH + y) * WW + x;
    float mx = 0.f;
#pragma unroll 4
    for (int d = 0; d < DD; d++) mx = fmaxf(mx, base[(size_t)d * HH * WW]);
#pragma unroll 4
    for (int d = 0; d < DD; d++) {
        float v = base[(size_t)d * HH * WW];
        if (v == 0.f) base[(size_t)d * HH * WW] = mx;
    }
}

// ---------------------------------------------------------------------------
extern "C" void kernel_launch(void* const* d_in, const int* in_sizes, int n_in,
                              void* d_out, int out_size) {
    const float* current_feats = (const float*)d_in[0];  // [B,C,H,W]
    const float* lookup_feats = (const float*)d_in[1];   // [B,F,C,H,W]
    const float* poses = (const float*)d_in[2];          // [B,F,4,4]
    const float* K = (const float*)d_in[3];              // [B,4,4]
    const float* invK = (const float*)d_in[4];           // [B,4,4]
    const float* depth_bins = (const float*)d_in[5];     // [D]
    float* out = (float*)d_out;                          // [B,D,H,W]

    setup_kernel<<<1, 32>>>(K, poses);

    // transpose lookup feats: nbf = B*F, and current feats: nbf = B
    float* lkT;
    float* curT;
    cudaGetSymbolAddress((void**)&lkT, g_lkT);
    cudaGetSymbolAddress((void**)&curT, g_curT);
    transpose_kernel<<<BB * FF * (NPIX / 32), 256>>>(lookup_feats, lkT);
    transpose_kernel<<<BB * (NPIX / 32), 256>>>(current_feats, curT);

    const int TOT = BB * DD * HH * WW;  // 638976 warps
    int blocks = (TOT * 32 + 255) / 256;
    cost_kernel<<<blocks, 256>>>(invK, depth_bins, out);

    int npx = BB * HH * WW;
    fix_kernel<<<(npx + 255) / 256, 256>>>(out);
}

// round 6
// speedup vs baseline: 1.8125x; 1.8125x over previous
#include <cuda_runtime.h>

// Problem constants (fixed shapes from the reference)
#define BB 2
#define FF 2
#define CC 64
#define HH 32
#define WW 104
#define DD 96
#define NPIX (HH * WW)          // 3328
#define EPSV 1e-7f
#define ND 8                    // depth bins per warp
#define DG (DD / ND)            // 12 depth groups

// Scratch (device globals; no allocation allowed)
__device__ float g_lkT[BB * FF * NPIX * CC];   // [B,F,H,W,C]
__device__ float g_curT[BB * NPIX * CC];       // [B,H,W,C]
__device__ float g_P[BB * FF * 12];            // (K @ pose)[:3,:4]
__device__ float g_valid[BB * FF];

// ---------------------------------------------------------------------------
// Setup: P = (K @ pose)[:3,:], valid = (sum(pose) != 0)
// ---------------------------------------------------------------------------
__global__ void setup_kernel(const float* __restrict__ K,
                             const float* __restrict__ poses) {
    int t = threadIdx.x;
    if (t >= BB * FF) return;
    int b = t / FF;
    const float* Kb = K + b * 16;
    const float* ps = poses + t * 16;
    float s = 0.f;
#pragma unroll
    for (int i = 0; i < 16; i++) s += ps[i];
    g_valid[t] = (s != 0.f) ? 1.f : 0.f;
#pragma unroll
    for (int i = 0; i < 3; i++)
#pragma unroll
        for (int j = 0; j < 4; j++) {
            float acc = 0.f;
#pragma unroll
            for (int k = 0; k < 4; k++) acc += Kb[i * 4 + k] * ps[k * 4 + j];
            g_P[t * 12 + i * 4 + j] = acc;
        }
}

// ---------------------------------------------------------------------------
// Fused transpose: [nbf, C, NPIX] -> [nbf, NPIX, C]. First BB*FF*104 blocks
// handle lookup feats, remaining BB*104 handle current feats.
// ---------------------------------------------------------------------------
__global__ __launch_bounds__(256) void transpose_kernel(
    const float* __restrict__ lk_in, const float* __restrict__ cur_in) {
    __shared__ float tile[CC][33];
    const int ntiles = NPIX / 32;  // 104
    int blk = blockIdx.x;
    const float* in;
    float* out;
    int bf;
    if (blk < BB * FF * ntiles) {
        bf = blk / ntiles;
        in = lk_in + (size_t)bf * CC * NPIX;
        out = g_lkT + (size_t)bf * NPIX * CC;
    } else {
        blk -= BB * FF * ntiles;
        bf = blk / ntiles;
        in = cur_in + (size_t)bf * CC * NPIX;
        out = g_curT + (size_t)bf * NPIX * CC;
    }
    int p0 = (blk % ntiles) * 32;
    int t = threadIdx.x;
    {
        int tx = t & 31, ty = t >> 5;
#pragma unroll
        for (int c = ty; c < CC; c += 8)
            tile[c][tx] = in[c * NPIX + p0 + tx];
    }
    __syncthreads();
    {
        int wx = t & 63, wy = t >> 6;
#pragma unroll
        for (int pl = wy; pl < 32; pl += 4)
            out[(p0 + pl) * CC + wx] = tile[wx][pl];
    }
}

// ---------------------------------------------------------------------------
// Main cost kernel: one warp per (b, dgroup, y, x); ND=8 depth bins per warp.
// Lane l owns channels {2l, 2l+1}. Frames merged before the cross-lane
// reduction; all 8 depth-bin reductions done by one batched select-swap
// butterfly; 8 predicated stores from 8 lanes.
// ---------------------------------------------------------------------------
__global__ __launch_bounds__(256) void cost_kernel(
    const float* __restrict__ invK, const float* __restrict__ depth_bins,
    float* __restrict__ out) {
    int gtid = blockIdx.x * blockDim.x + threadIdx.x;
    int warp = gtid >> 5;
    int lane = gtid & 31;
    const int TOTW = BB * DG * HH * WW;  // 79872
    if (warp >= TOTW) return;

    int x = warp % WW;
    int t = warp / WW;
    int y = t % HH;
    t /= HH;
    int dg = t % DG;
    int b = t / DG;
    int dbase = dg * ND;

    float* outp = out + (((size_t)b * DD + dbase) * HH + y) * WW + x;

    // border pixels: whole D-column is 0 (fix kernel leaves zeros intact)
    if (y < 2 || y >= HH - 2 || x < 2 || x >= WW - 2) {
        if (lane < ND) outp[(size_t)lane * NPIX] = 0.f;
        return;
    }

    const float* iv = invK + b * 16;
    float fx = (float)x, fy = (float)y;
    float camx = iv[0] * fx + iv[1] * fy + iv[2];
    float camy = iv[4] * fx + iv[5] * fy + iv[6];
    float camz = iv[8] * fx + iv[9] * fy + iv[10];

    // per-frame ray transform: cpts = d * (P3x3 . cam) + P[:,3]
    float a0[FF], a1[FF], a2[FF], t0[FF], t1[FF], t2[FF], vfr[FF];
#pragma unroll
    for (int f = 0; f < FF; f++) {
        const float* P = g_P + (b * FF + f) * 12;
        a0[f] = P[0] * camx + P[1] * camy + P[2] * camz;
        a1[f] = P[4] * camx + P[5] * camy + P[6] * camz;
        a2[f] = P[8] * camx + P[9] * camy + P[10] * camz;
        t0[f] = P[3];
        t1[f] = P[7];
        t2[f] = P[11];
        vfr[f] = g_valid[b * FF + f];
    }

    float2 cur =
        ((const float2*)(g_curT + ((size_t)(b * HH + y) * WW + x) * CC))[lane];

    float s[ND];              // per-lane, per-depth accumulators (f merged)
    unsigned cnt_packed = 0;  // 2 bits per depth bin, warp-uniform

#pragma unroll
    for (int j = 0; j < ND; j++) {
        float depth = __ldg(depth_bins + dbase + j);
        float sj = 0.f;
        int cj = 0;
#pragma unroll
        for (int f = 0; f < FF; f++) {
            float c0 = fmaf(a0[f], depth, t0[f]);
            float c1 = fmaf(a1[f], depth, t1[f]);
            float c2 = fmaf(a2[f], depth, t2[f]);
            float inv = __fdividef(1.f, c2 + EPSV);
            float u = c0 * inv;
            float v = c1 * inv;
            // warp-uniform branch (u, v identical across lanes)
            if (u >= 2.f && u <= (float)(WW - 2) && v >= 2.f &&
                v <= (float)(HH - 2)) {
                float xf = floorf(u), yf = floorf(v);
                int xi = (int)xf, yi = (int)yf;
                float wx = u - xf, wy = v - yf;
                const float2* lk =
                    (const float2*)(g_lkT +
                                    ((size_t)((b * FF + f) * HH + yi) * WW + xi) *
                                        CC);
                float2 v00 = lk[lane];
                float2 v01 = lk[lane + 32];           // +1 pixel in x
                float2 v10 = lk[lane + WW * 32];      // +1 pixel in y
                float2 v11 = lk[lane + WW * 32 + 32];
                // lerp-form bilinear
                float i0x = v00.x + wx * (v01.x - v00.x);
                float i0y = v00.y + wx * (v01.y - v00.y);
                float i1x = v10.x + wx * (v11.x - v10.x);
                float i1y = v10.y + wx * (v11.y - v10.y);
                float sx = i0x + wy * (i1x - i0x);
                float sy = i0y + wy * (i1y - i0y);
                float acc = fabsf(sx - cur.x) + fabsf(sy - cur.y);
                unsigned bal = __ballot_sync(0xffffffffu, acc > 0.f);
                sj = fmaf(vfr[f], acc, sj);
                cj += (bal != 0u && vfr[f] > 0.f) ? 1 : 0;
            }
        }
        s[j] = sj;
        cnt_packed |= (unsigned)cj << (2 * j);
    }

    // Batched 8-way warp reduction (select-swap butterfly).
    // After all stages, each lane holds the full warp sum for depth bin
    // d_idx = 4*b4 + 2*b8 + b16  (lane bit decomposition).
    bool b16 = (lane & 16) != 0;
    bool b8 = (lane & 8) != 0;
    bool b4 = (lane & 4) != 0;
    float w[4];
#pragma unroll
    for (int i = 0; i < 4; i++) {
        float keep = b16 ? s[2 * i + 1] : s[2 * i];
        float send = b16 ? s[2 * i] : s[2 * i + 1];
        w[i] = keep + __shfl_xor_sync(0xffffffffu, send, 16);
    }
    float u2[2];
#pragma unroll
    for (int i = 0; i < 2; i++) {
        float keep = b8 ? w[2 * i + 1] : w[2 * i];
        float send = b8 ? w[2 * i] : w[2 * i + 1];
        u2[i] = keep + __shfl_xor_sync(0xffffffffu, send, 8);
    }
    float r;
    {
        float keep = b4 ? u2[1] : u2[0];
        float send = b4 ? u2[0] : u2[1];
        r = keep + __shfl_xor_sync(0xffffffffu, send, 4);
    }
    r += __shfl_xor_sync(0xffffffffu, r, 2);
    r += __shfl_xor_sync(0xffffffffu, r, 1);

    int didx = ((lane >> 2) & 1) * 4 + ((lane >> 3) & 1) * 2 + ((lane >> 4) & 1);
    if ((lane & 3) == 0) {
        float cf = (float)((cnt_packed >> (2 * didx)) & 3u);
        outp[(size_t)didx * NPIX] = __fdividef(r * (1.0f / CC), cf + EPSV);
    }
}

// ---------------------------------------------------------------------------
// D-axis fixup: cost==0 -> max over D (computed on pre-fix values)
// ---------------------------------------------------------------------------
__global__ void fix_kernel(float* __restrict__ out) {
    int tid = blockIdx.x * blockDim.x + threadIdx.x;
    if (tid >= BB * HH * WW) return;
    int x = tid % WW;
    int y = (tid / WW) % HH;
    int b = tid / (WW * HH);
    float* base = out + ((size_t)b * DD * HH + y) * WW + x;
    float mx = 0.f;
#pragma unroll 4
    for (int d = 0; d < DD; d++) mx = fmaxf(mx, base[(size_t)d * NPIX]);
#pragma unroll 4
    for (int d = 0; d < DD; d++) {
        float v = base[(size_t)d * NPIX];
        if (v == 0.f) base[(size_t)d * NPIX] = mx;
    }
}

// ---------------------------------------------------------------------------
extern "C" void kernel_launch(void* const* d_in, const int* in_sizes, int n_in,
                              void* d_out, int out_size) {
    const float* current_feats = (const float*)d_in[0];  // [B,C,H,W]
    const float* lookup_feats = (const float*)d_in[1];   // [B,F,C,H,W]
    const float* poses = (const float*)d_in[2];          // [B,F,4,4]
    const float* K = (const float*)d_in[3];              // [B,4,4]
    const float* invK = (const float*)d_in[4];           // [B,4,4]
    const float* depth_bins = (const float*)d_in[5];     // [D]
    float* out = (float*)d_out;                          // [B,D,H,W]

    setup_kernel<<<1, 32>>>(K, poses);

    const int ntiles = NPIX / 32;  // 104
    transpose_kernel<<<(BB * FF + BB) * ntiles, 256>>>(lookup_feats,
                                                       current_feats);

    const int TOTW = BB * DG * HH * WW;  // 79872 warps
    int blocks = (TOTW * 32 + 255) / 256;
    cost_kernel<<<blocks, 256>>>(invK, depth_bins, out);

    int npx = BB * HH * WW;
    fix_kernel<<<(npx + 255) / 256, 256>>>(out);
}

// round 7
// speedup vs baseline: 1.9727x; 1.0884x over previous
#include <cuda_runtime.h>

// Problem constants (fixed shapes from the reference)
#define BB 2
#define FF 2
#define CC 64
#define HH 32
#define WW 104
#define DD 96
#define NPIX (HH * WW)          // 3328
#define EPSV 1e-7f
#define ND 8                    // depth bins per warp
#define DG (DD / ND)            // 12 depth groups

// Scratch (device globals; no allocation allowed)
__device__ float g_lkT[BB * FF * NPIX * CC];   // [B,F,H,W,C]
__device__ float g_curT[BB * NPIX * CC];       // [B,H,W,C]
__device__ float g_P[BB * FF * 12];            // (K @ pose)[:3,:4]
__device__ float g_valid[BB * FF];

// ---------------------------------------------------------------------------
// Fused transpose: [nbf, C, NPIX] -> [nbf, NPIX, C]. First BB*FF*104 blocks
// handle lookup feats, remaining BB*104 handle current feats. Block 0 also
// computes P = (K @ pose)[:3,:] and the validity flags (threads 0..3).
// ---------------------------------------------------------------------------
__global__ __launch_bounds__(256) void transpose_kernel(
    const float* __restrict__ lk_in, const float* __restrict__ cur_in,
    const float* __restrict__ K, const float* __restrict__ poses) {
    __shared__ float tile[CC][33];
    const int ntiles = NPIX / 32;  // 104

    if (blockIdx.x == 0 && threadIdx.x < BB * FF) {
        int tt = threadIdx.x;
        int b = tt / FF;
        const float* Kb = K + b * 16;
        const float* ps = poses + tt * 16;
        float s = 0.f;
#pragma unroll
        for (int i = 0; i < 16; i++) s += ps[i];
        g_valid[tt] = (s != 0.f) ? 1.f : 0.f;
#pragma unroll
        for (int i = 0; i < 3; i++)
#pragma unroll
            for (int j = 0; j < 4; j++) {
                float acc = 0.f;
#pragma unroll
                for (int k = 0; k < 4; k++)
                    acc += Kb[i * 4 + k] * ps[k * 4 + j];
                g_P[tt * 12 + i * 4 + j] = acc;
            }
    }

    int blk = blockIdx.x;
    const float* in;
    float* out;
    int bf;
    if (blk < BB * FF * ntiles) {
        bf = blk / ntiles;
        in = lk_in + (size_t)bf * CC * NPIX;
        out = g_lkT + (size_t)bf * NPIX * CC;
    } else {
        blk -= BB * FF * ntiles;
        bf = blk / ntiles;
        in = cur_in + (size_t)bf * CC * NPIX;
        out = g_curT + (size_t)bf * NPIX * CC;
    }
    int p0 = (blk % ntiles) * 32;
    int t = threadIdx.x;
    {
        int tx = t & 31, ty = t >> 5;
#pragma unroll
        for (int c = ty; c < CC; c += 8)
            tile[c][tx] = in[c * NPIX + p0 + tx];
    }
    __syncthreads();
    {
        int wx = t & 63, wy = t >> 6;
#pragma unroll
        for (int pl = wy; pl < 32; pl += 4)
            out[(p0 + pl) * CC + wx] = tile[wx][pl];
    }
}

// ---------------------------------------------------------------------------
// Main cost kernel: one warp per (b, dgroup, y, x); ND=8 depth bins per warp.
// Lane l owns channels {2l, 2l+1}. Frames merged before the cross-lane
// reduction; all 8 depth-bin reductions done by one batched select-swap
// butterfly; 8 predicated stores from 8 lanes.
// ---------------------------------------------------------------------------
__global__ __launch_bounds__(256) void cost_kernel(
    const float* __restrict__ invK, const float* __restrict__ depth_bins,
    float* __restrict__ out) {
    int gtid = blockIdx.x * blockDim.x + threadIdx.x;
    int warp = gtid >> 5;
    int lane = gtid & 31;
    const int TOTW = BB * DG * HH * WW;  // 79872
    if (warp >= TOTW) return;

    int x = warp % WW;
    int t = warp / WW;
    int y = t % HH;
    t /= HH;
    int dg = t % DG;
    int b = t / DG;
    int dbase = dg * ND;

    float* outp = out + (((size_t)b * DD + dbase) * HH + y) * WW + x;

    // border pixels: whole D-column is 0 (fix kernel leaves zeros intact)
    if (y < 2 || y >= HH - 2 || x < 2 || x >= WW - 2) {
        if (lane < ND) outp[(size_t)lane * NPIX] = 0.f;
        return;
    }

    const float* iv = invK + b * 16;
    float fx = (float)x, fy = (float)y;
    float camx = iv[0] * fx + iv[1] * fy + iv[2];
    float camy = iv[4] * fx + iv[5] * fy + iv[6];
    float camz = iv[8] * fx + iv[9] * fy + iv[10];

    // per-frame ray transform: cpts = d * (P3x3 . cam) + P[:,3]
    float a0[FF], a1[FF], a2[FF], t0[FF], t1[FF], t2[FF], vfr[FF];
#pragma unroll
    for (int f = 0; f < FF; f++) {
        const float* P = g_P + (b * FF + f) * 12;
        a0[f] = P[0] * camx + P[1] * camy + P[2] * camz;
        a1[f] = P[4] * camx + P[5] * camy + P[6] * camz;
        a2[f] = P[8] * camx + P[9] * camy + P[10] * camz;
        t0[f] = P[3];
        t1[f] = P[7];
        t2[f] = P[11];
        vfr[f] = g_valid[b * FF + f];
    }

    float2 cur =
        ((const float2*)(g_curT + ((size_t)(b * HH + y) * WW + x) * CC))[lane];

    float s[ND];              // per-lane, per-depth accumulators (f merged)
    unsigned cnt_packed = 0;  // 2 bits per depth bin, warp-uniform

#pragma unroll
    for (int j = 0; j < ND; j++) {
        float depth = __ldg(depth_bins + dbase + j);
        float sj = 0.f;
        int cj = 0;
#pragma unroll
        for (int f = 0; f < FF; f++) {
            float c0 = fmaf(a0[f], depth, t0[f]);
            float c1 = fmaf(a1[f], depth, t1[f]);
            float c2 = fmaf(a2[f], depth, t2[f]);
            float inv = __fdividef(1.f, c2 + EPSV);
            float u = c0 * inv;
            float v = c1 * inv;
            // warp-uniform branch (u, v identical across lanes)
            if (u >= 2.f && u <= (float)(WW - 2) && v >= 2.f &&
                v <= (float)(HH - 2)) {
                float xf = floorf(u), yf = floorf(v);
                int xi = (int)xf, yi = (int)yf;
                float wx = u - xf, wy = v - yf;
                const float2* lk =
                    (const float2*)(g_lkT +
                                    ((size_t)((b * FF + f) * HH + yi) * WW + xi) *
                                        CC);
                float2 v00 = lk[lane];
                float2 v01 = lk[lane + 32];           // +1 pixel in x
                float2 v10 = lk[lane + WW * 32];      // +1 pixel in y
                float2 v11 = lk[lane + WW * 32 + 32];
                // lerp-form bilinear
                float i0x = v00.x + wx * (v01.x - v00.x);
                float i0y = v00.y + wx * (v01.y - v00.y);
                float i1x = v10.x + wx * (v11.x - v10.x);
                float i1y = v10.y + wx * (v11.y - v10.y);
                float sx = i0x + wy * (i1x - i0x);
                float sy = i0y + wy * (i1y - i0y);
                float acc = fabsf(sx - cur.x) + fabsf(sy - cur.y);
                unsigned bal = __ballot_sync(0xffffffffu, acc > 0.f);
                sj = fmaf(vfr[f], acc, sj);
                cj += (bal != 0u && vfr[f] > 0.f) ? 1 : 0;
            }
        }
        s[j] = sj;
        cnt_packed |= (unsigned)cj << (2 * j);
    }

    // Batched 8-way warp reduction (select-swap butterfly).
    bool b16 = (lane & 16) != 0;
    bool b8 = (lane & 8) != 0;
    bool b4 = (lane & 4) != 0;
    float w[4];
#pragma unroll
    for (int i = 0; i < 4; i++) {
        float keep = b16 ? s[2 * i + 1] : s[2 * i];
        float send = b16 ? s[2 * i] : s[2 * i + 1];
        w[i] = keep + __shfl_xor_sync(0xffffffffu, send, 16);
    }
    float u2[2];
#pragma unroll
    for (int i = 0; i < 2; i++) {
        float keep = b8 ? w[2 * i + 1] : w[2 * i];
        float send = b8 ? w[2 * i] : w[2 * i + 1];
        u2[i] = keep + __shfl_xor_sync(0xffffffffu, send, 8);
    }
    float r;
    {
        float keep = b4 ? u2[1] : u2[0];
        float send = b4 ? u2[0] : u2[1];
        r = keep + __shfl_xor_sync(0xffffffffu, send, 4);
    }
    r += __shfl_xor_sync(0xffffffffu, r, 2);
    r += __shfl_xor_sync(0xffffffffu, r, 1);

    int didx = ((lane >> 2) & 1) * 4 + ((lane >> 3) & 1) * 2 + ((lane >> 4) & 1);
    if ((lane & 3) == 0) {
        float cf = (float)((cnt_packed >> (2 * didx)) & 3u);
        outp[(size_t)didx * NPIX] = __fdividef(r * (1.0f / CC), cf + EPSV);
    }
}

// ---------------------------------------------------------------------------
// D-axis fixup: cost==0 -> max over D. One block per (b,y) row: thread =
// pixel x, fully unrolled D walk -> high MLP, 64 blocks for latency spread.
// ---------------------------------------------------------------------------
__global__ __launch_bounds__(128) void fix_kernel(float* __restrict__ out) {
    int by = blockIdx.x;           // 0 .. BB*HH-1
    int b = by / HH;
    int y = by % HH;
    int x = threadIdx.x;
    if (x >= WW) return;
    float* base = out + ((size_t)b * DD * HH + y) * WW + x;
    float mx = 0.f;
#pragma unroll
    for (int d = 0; d < DD; d++) mx = fmaxf(mx, base[(size_t)d * NPIX]);
#pragma unroll
    for (int d = 0; d < DD; d++) {
        float v = base[(size_t)d * NPIX];
        if (v == 0.f) base[(size_t)d * NPIX] = mx;
    }
}

// ---------------------------------------------------------------------------
extern "C" void kernel_launch(void* const* d_in, const int* in_sizes, int n_in,
                              void* d_out, int out_size) {
    const float* current_feats = (const float*)d_in[0];  // [B,C,H,W]
    const float* lookup_feats = (const float*)d_in[1];   // [B,F,C,H,W]
    const float* poses = (const float*)d_in[2];          // [B,F,4,4]
    const float* K = (const float*)d_in[3];              // [B,4,4]
    const float* invK = (const float*)d_in[4];           // [B,4,4]
    const float* depth_bins = (const float*)d_in[5];     // [D]
    float* out = (float*)d_out;                          // [B,D,H,W]

    const int ntiles = NPIX / 32;  // 104
    transpose_kernel<<<(BB * FF + BB) * ntiles, 256>>>(lookup_feats,
                                                       current_feats, K, poses);

    const int TOTW = BB * DG * HH * WW;  // 79872 warps
    int blocks = (TOTW * 32 + 255) / 256;
    cost_kernel<<<blocks, 256>>>(invK, depth_bins, out);

    fix_kernel<<<BB * HH, 128>>>(out);
}

// round 8
// speedup vs baseline: 2.7572x; 1.3977x over previous
#include <cuda_runtime.h>

// Problem constants (fixed shapes from the reference)
#define BB 2
#define FF 2
#define CC 64
#define HH 32
#define WW 104
#define DD 96
#define NPIX (HH * WW)          // 3328
#define EPSV 1e-7f
#define ND 8                    // depth bins per warp
#define DG (DD / ND)            // 12 depth groups

// Scratch (device globals; no allocation allowed)
__device__ float g_lkT[BB * FF * NPIX * CC];   // [B,F,H,W,C]
__device__ float g_curT[BB * NPIX * CC];       // [B,H,W,C]
__device__ float g_P[BB * FF * 12];            // (K @ pose)[:3,:4]
__device__ float g_valid[BB * FF];

// ---------------------------------------------------------------------------
// Fused transpose: [nbf, C, NPIX] -> [nbf, NPIX, C]. First BB*FF*104 blocks
// handle lookup feats, remaining BB*104 handle current feats. Block 0 also
// computes P = (K @ pose)[:3,:] and the validity flags (threads 0..3).
// ---------------------------------------------------------------------------
__global__ __launch_bounds__(256) void transpose_kernel(
    const float* __restrict__ lk_in, const float* __restrict__ cur_in,
    const float* __restrict__ K, const float* __restrict__ poses) {
    __shared__ float tile[CC][33];
    const int ntiles = NPIX / 32;  // 104

    if (blockIdx.x == 0 && threadIdx.x < BB * FF) {
        int tt = threadIdx.x;
        int b = tt / FF;
        const float* Kb = K + b * 16;
        const float* ps = poses + tt * 16;
        float s = 0.f;
#pragma unroll
        for (int i = 0; i < 16; i++) s += ps[i];
        g_valid[tt] = (s != 0.f) ? 1.f : 0.f;
#pragma unroll
        for (int i = 0; i < 3; i++)
#pragma unroll
            for (int j = 0; j < 4; j++) {
                float acc = 0.f;
#pragma unroll
                for (int k = 0; k < 4; k++)
                    acc += Kb[i * 4 + k] * ps[k * 4 + j];
                g_P[tt * 12 + i * 4 + j] = acc;
            }
    }

    int blk = blockIdx.x;
    const float* in;
    float* out;
    int bf;
    if (blk < BB * FF * ntiles) {
        bf = blk / ntiles;
        in = lk_in + (size_t)bf * CC * NPIX;
        out = g_lkT + (size_t)bf * NPIX * CC;
    } else {
        blk -= BB * FF * ntiles;
        bf = blk / ntiles;
        in = cur_in + (size_t)bf * CC * NPIX;
        out = g_curT + (size_t)bf * NPIX * CC;
    }
    int p0 = (blk % ntiles) * 32;
    int t = threadIdx.x;
    {
        int tx = t & 31, ty = t >> 5;
#pragma unroll
        for (int c = ty; c < CC; c += 8)
            tile[c][tx] = in[c * NPIX + p0 + tx];
    }
    __syncthreads();
    {
        int wx = t & 63, wy = t >> 6;
#pragma unroll
        for (int pl = wy; pl < 32; pl += 4)
            out[(p0 + pl) * CC + wx] = tile[wx][pl];
    }
}

// ---------------------------------------------------------------------------
// Main cost kernel: one warp per (b, dgroup, y, x); ND=8 depth bins per warp.
// Lane l owns channels {2l, 2l+1} for the feature loads.
// Geometry (projection, rcp, bounds, weights, address) for the 16 (depth,
// frame) cases is computed ONCE in lanes 0..15 (src lane = 2*j+f), then
// broadcast with 3 shuffles per case. All 8 depth-bin reductions done by one
// batched select-swap butterfly; 8 predicated stores from 8 lanes.
// ---------------------------------------------------------------------------
__global__ __launch_bounds__(256) void cost_kernel(
    const float* __restrict__ invK, const float* __restrict__ depth_bins,
    float* __restrict__ out) {
    int gtid = blockIdx.x * blockDim.x + threadIdx.x;
    int warp = gtid >> 5;
    int lane = gtid & 31;
    const int TOTW = BB * DG * HH * WW;  // 79872
    if (warp >= TOTW) return;

    int x = warp % WW;
    int t = warp / WW;
    int y = t % HH;
    t /= HH;
    int dg = t % DG;
    int b = t / DG;
    int dbase = dg * ND;

    float* outp = out + (((size_t)b * DD + dbase) * HH + y) * WW + x;

    // border pixels: whole D-column is 0 (fix kernel leaves zeros intact)
    if (y < 2 || y >= HH - 2 || x < 2 || x >= WW - 2) {
        if (lane < ND) outp[(size_t)lane * NPIX] = 0.f;
        return;
    }

    const float* iv = invK + b * 16;
    float fx = (float)x, fy = (float)y;
    float camx = iv[0] * fx + iv[1] * fy + iv[2];
    float camy = iv[4] * fx + iv[5] * fy + iv[6];
    float camz = iv[8] * fx + iv[9] * fy + iv[10];

    // per-frame ray transform scalars: cpts = d * (P3x3 . cam) + P[:,3]
    const float* P0 = g_P + (b * FF + 0) * 12;
    const float* P1 = g_P + (b * FF + 1) * 12;
    float a00 = P0[0] * camx + P0[1] * camy + P0[2] * camz;
    float a10 = P0[4] * camx + P0[5] * camy + P0[6] * camz;
    float a20 = P0[8] * camx + P0[9] * camy + P0[10] * camz;
    float a01 = P1[0] * camx + P1[1] * camy + P1[2] * camz;
    float a11 = P1[4] * camx + P1[5] * camy + P1[6] * camz;
    float a21 = P1[8] * camx + P1[9] * camy + P1[10] * camz;
    float vf0 = g_valid[b * FF + 0];
    float vf1 = g_valid[b * FF + 1];

    float2 cur =
        ((const float2*)(g_curT + ((size_t)(b * HH + y) * WW + x) * CC))[lane];

    // --- geometry, computed once in lanes 0..15 (src = 2*j + f = lane) ---
    int gj = (lane >> 1) & 7;  // depth index (clamped so depth read in-range)
    int gf = lane & 1;         // frame index
    float depth = __ldg(depth_bins + dbase + gj);
    float A0 = gf ? a01 : a00;
    float A1 = gf ? a11 : a10;
    float A2 = gf ? a21 : a20;
    float T0 = gf ? P1[3] : P0[3];
    float T1 = gf ? P1[7] : P0[7];
    float T2 = gf ? P1[11] : P0[11];
    float c0 = fmaf(A0, depth, T0);
    float c1 = fmaf(A1, depth, T1);
    float c2 = fmaf(A2, depth, T2);
    float invz = __fdividef(1.f, c2 + EPSV);
    float u = c0 * invz;
    float v = c1 * invz;
    bool inb = (lane < 16) && (u >= 2.f) && (u <= (float)(WW - 2)) &&
               (v >= 2.f) && (v <= (float)(HH - 2));
    unsigned inmask = __ballot_sync(0xffffffffu, inb);
    float xf = floorf(u), yf = floorf(v);
    float wxg = u - xf;
    float wyg = v - yf;
    int offg = ((gf * HH + (int)yf) * WW + (int)xf) * CC;

    const float* lkb = g_lkT + (size_t)b * FF * NPIX * CC;

    float s[ND];              // per-lane, per-depth accumulators (f merged)
    unsigned cnt_packed = 0;  // 2 bits per depth bin, warp-uniform

#pragma unroll
    for (int j = 0; j < ND; j++) {
        float sj = 0.f;
        int cj = 0;
#pragma unroll
        for (int f = 0; f < FF; f++) {
            int src = 2 * j + f;
            if (inmask & (1u << src)) {  // warp-uniform
                int off = __shfl_sync(0xffffffffu, offg, src);
                float wx = __shfl_sync(0xffffffffu, wxg, src);
                float wy = __shfl_sync(0xffffffffu, wyg, src);
                const float2* lk = (const float2*)(lkb + off);
                float2 v00 = lk[lane];
                float2 v01 = lk[lane + 32];           // +1 pixel in x
                float2 v10 = lk[lane + WW * 32];      // +1 pixel in y
                float2 v11 = lk[lane + WW * 32 + 32];
                // lerp-form bilinear
                float i0x = v00.x + wx * (v01.x - v00.x);
                float i0y = v00.y + wx * (v01.y - v00.y);
                float i1x = v10.x + wx * (v11.x - v10.x);
                float i1y = v10.y + wx * (v11.y - v10.y);
                float sx = i0x + wy * (i1x - i0x);
                float sy = i0y + wy * (i1y - i0y);
                float acc = fabsf(sx - cur.x) + fabsf(sy - cur.y);
                unsigned bal = __ballot_sync(0xffffffffu, acc > 0.f);
                float vf = f ? vf1 : vf0;
                sj = fmaf(vf, acc, sj);
                cj += (bal != 0u && vf > 0.f) ? 1 : 0;
            }
        }
        s[j] = sj;
        cnt_packed |= (unsigned)cj << (2 * j);
    }

    // Batched 8-way warp reduction (select-swap butterfly).
    bool b16 = (lane & 16) != 0;
    bool b8 = (lane & 8) != 0;
    bool b4 = (lane & 4) != 0;
    float w[4];
#pragma unroll
    for (int i = 0; i < 4; i++) {
        float keep = b16 ? s[2 * i + 1] : s[2 * i];
        float send = b16 ? s[2 * i] : s[2 * i + 1];
        w[i] = keep + __shfl_xor_sync(0xffffffffu, send, 16);
    }
    float u2[2];
#pragma unroll
    for (int i = 0; i < 2; i++) {
        float keep = b8 ? w[2 * i + 1] : w[2 * i];
        float send = b8 ? w[2 * i] : w[2 * i + 1];
        u2[i] = keep + __shfl_xor_sync(0xffffffffu, send, 8);
    }
    float r;
    {
        float keep = b4 ? u2[1] : u2[0];
        float send = b4 ? u2[0] : u2[1];
        r = keep + __shfl_xor_sync(0xffffffffu, send, 4);
    }
    r += __shfl_xor_sync(0xffffffffu, r, 2);
    r += __shfl_xor_sync(0xffffffffu, r, 1);

    int didx = ((lane >> 2) & 1) * 4 + ((lane >> 3) & 1) * 2 + ((lane >> 4) & 1);
    if ((lane & 3) == 0) {
        float cf = (float)((cnt_packed >> (2 * didx)) & 3u);
        outp[(size_t)didx * NPIX] = __fdividef(r * (1.0f / CC), cf + EPSV);
    }
}

// ---------------------------------------------------------------------------
// D-axis fixup: cost==0 -> max over D. One block per (b,y) row: thread =
// pixel x, fully unrolled D walk -> high MLP, 64 blocks for latency spread.
// ---------------------------------------------------------------------------
__global__ __launch_bounds__(128) void fix_kernel(float* __restrict__ out) {
    int by = blockIdx.x;           // 0 .. BB*HH-1
    int b = by / HH;
    int y = by % HH;
    int x = threadIdx.x;
    if (x >= WW) return;
    float* base = out + ((size_t)b * DD * HH + y) * WW + x;
    float mx = 0.f;
#pragma unroll
    for (int d = 0; d < DD; d++) mx = fmaxf(mx, base[(size_t)d * NPIX]);
#pragma unroll
    for (int d = 0; d < DD; d++) {
        float v = base[(size_t)d * NPIX];
        if (v == 0.f) base[(size_t)d * NPIX] = mx;
    }
}

// ---------------------------------------------------------------------------
extern "C" void kernel_launch(void* const* d_in, const int* in_sizes, int n_in,
                              void* d_out, int out_size) {
    const float* current_feats = (const float*)d_in[0];  // [B,C,H,W]
    const float* lookup_feats = (const float*)d_in[1];   // [B,F,C,H,W]
    const float* poses = (const float*)d_in[2];          // [B,F,4,4]
    const float* K = (const float*)d_in[3];              // [B,4,4]
    const float* invK = (const float*)d_in[4];           // [B,4,4]
    const float* depth_bins = (const float*)d_in[5];     // [D]
    float* out = (float*)d_out;                          // [B,D,H,W]

    const int ntiles = NPIX / 32;  // 104
    transpose_kernel<<<(BB * FF + BB) * ntiles, 256>>>(lookup_feats,
                                                       current_feats, K, poses);

    const int TOTW = BB * DG * HH * WW;  // 79872 warps
    int blocks = (TOTW * 32 + 255) / 256;
    cost_kernel<<<blocks, 256>>>(invK, depth_bins, out);

    fix_kernel<<<BB * HH, 128>>>(out);
}

// round 10
// speedup vs baseline: 3.5375x; 1.2830x over previous
#include <cuda_runtime.h>
#include <cuda_fp16.h>

// Problem constants (fixed shapes from the reference)
#define BB 2
#define FF 2
#define CC 64
#define HH 32
#define WW 104
#define DD 96
#define NPIX (HH * WW)          // 3328
#define EPSV 1e-7f
#define ND 8                    // depth bins per warp
#define DG (DD / ND)            // 12 depth groups

// Scratch (device globals; no allocation allowed)
__device__ __half2 g_lkT[BB * FF * NPIX * (CC / 2)];  // [B,F,H,W,C/2] half2
__device__ __half2 g_curT[BB * NPIX * (CC / 2)];      // [B,H,W,C/2] half2
__device__ float g_P[BB * FF * 12];                   // (K @ pose)[:3,:4]
__device__ float g_valid[BB * FF];

// ---------------------------------------------------------------------------
// Fused transpose: [nbf, C, NPIX] fp32 -> [nbf, NPIX, C/2] half2. First
// BB*FF*104 blocks handle lookup feats, remaining BB*104 current feats.
// Block 0 also computes P = (K @ pose)[:3,:] and validity (threads 0..3).
// ---------------------------------------------------------------------------
__global__ __launch_bounds__(256) void transpose_kernel(
    const float* __restrict__ lk_in, const float* __restrict__ cur_in,
    const float* __restrict__ K, const float* __restrict__ poses) {
    __shared__ float tile[CC][33];
    const int ntiles = NPIX / 32;  // 104

    if (blockIdx.x == 0 && threadIdx.x < BB * FF) {
        int tt = threadIdx.x;
        int b = tt / FF;
        const float* Kb = K + b * 16;
        const float* ps = poses + tt * 16;
        float s = 0.f;
#pragma unroll
        for (int i = 0; i < 16; i++) s += ps[i];
        g_valid[tt] = (s != 0.f) ? 1.f : 0.f;
#pragma unroll
        for (int i = 0; i < 3; i++)
#pragma unroll
            for (int j = 0; j < 4; j++) {
                float acc = 0.f;
#pragma unroll
                for (int k = 0; k < 4; k++)
                    acc += Kb[i * 4 + k] * ps[k * 4 + j];
                g_P[tt * 12 + i * 4 + j] = acc;
            }
    }

    int blk = blockIdx.x;
    const float* in;
    __half2* out;
    int bf;
    if (blk < BB * FF * ntiles) {
        bf = blk / ntiles;
        in = lk_in + (size_t)bf * CC * NPIX;
        out = g_lkT + (size_t)bf * NPIX * (CC / 2);
    } else {
        blk -= BB * FF * ntiles;
        bf = blk / ntiles;
        in = cur_in + (size_t)bf * CC * NPIX;
        out = g_curT + (size_t)bf * NPIX * (CC / 2);
    }
    int p0 = (blk % ntiles) * 32;
    int t = threadIdx.x;
    {
        int tx = t & 31, ty = t >> 5;
#pragma unroll
        for (int c = ty; c < CC; c += 8)
            tile[c][tx] = in[c * NPIX + p0 + tx];
    }
    __syncthreads();
    {
        int cp = t & 31;       // channel pair 0..31
        int r0 = t >> 5;       // 0..7
#pragma unroll
        for (int pl = r0; pl < 32; pl += 8)
            out[(p0 + pl) * (CC / 2) + cp] =
                __floats2half2_rn(tile[2 * cp][pl], tile[2 * cp + 1][pl]);
    }
}

// ---------------------------------------------------------------------------
// Main cost kernel: one warp per (b, dgroup, y, x); ND=8 depth bins per warp.
// Lane l owns channels {2l, 2l+1} as one half2. Geometry for the 16
// (depth,frame) cases is computed once in lanes 0..15 (src = 2*j+f), then
// broadcast with 2 shuffles per case (offset + packed half2 weights).
// Bilinear lerp and abs-diff run in half2 (2 ch/instr); accumulation in fp32.
// All 8 depth-bin reductions via one batched select-swap butterfly.
// ---------------------------------------------------------------------------
__global__ __launch_bounds__(256) void cost_kernel(
    const float* __restrict__ invK, const float* __restrict__ depth_bins,
    float* __restrict__ out) {
    int gtid = blockIdx.x * blockDim.x + threadIdx.x;
    int warp = gtid >> 5;
    int lane = gtid & 31;
    const int TOTW = BB * DG * HH * WW;  // 79872
    if (warp >= TOTW) return;

    int x = warp % WW;
    int t = warp / WW;
    int y = t % HH;
    t /= HH;
    int dg = t % DG;
    int b = t / DG;
    int dbase = dg * ND;

    float* outp = out + (((size_t)b * DD + dbase) * HH + y) * WW + x;

    // border pixels: whole D-column is 0 (fix kernel leaves zeros intact)
    if (y < 2 || y >= HH - 2 || x < 2 || x >= WW - 2) {
        if (lane < ND) outp[(size_t)lane * NPIX] = 0.f;
        return;
    }

    const float* iv = invK + b * 16;
    float fx = (float)x, fy = (float)y;
    float camx = iv[0] * fx + iv[1] * fy + iv[2];
    float camy = iv[4] * fx + iv[5] * fy + iv[6];
    float camz = iv[8] * fx + iv[9] * fy + iv[10];

    const float* P0 = g_P + (b * FF + 0) * 12;
    const float* P1 = g_P + (b * FF + 1) * 12;
    float a00 = P0[0] * camx + P0[1] * camy + P0[2] * camz;
    float a10 = P0[4] * camx + P0[5] * camy + P0[6] * camz;
    float a20 = P0[8] * camx + P0[9] * camy + P0[10] * camz;
    float a01 = P1[0] * camx + P1[1] * camy + P1[2] * camz;
    float a11 = P1[4] * camx + P1[5] * camy + P1[6] * camz;
    float a21 = P1[8] * camx + P1[9] * camy + P1[10] * camz;
    float vf0 = g_valid[b * FF + 0];
    float vf1 = g_valid[b * FF + 1];

    __half2 cur = g_curT[((size_t)(b * HH + y) * WW + x) * (CC / 2) + lane];

    // --- geometry, computed once in lanes 0..15 (src = 2*j + f = lane) ---
    int gj = (lane >> 1) & 7;
    int gf = lane & 1;
    float depth = __ldg(depth_bins + dbase + gj);
    float A0 = gf ? a01 : a00;
    float A1 = gf ? a11 : a10;
    float A2 = gf ? a21 : a20;
    float T0 = gf ? P1[3] : P0[3];
    float T1 = gf ? P1[7] : P0[7];
    float T2 = gf ? P1[11] : P0[11];
    float c0 = fmaf(A0, depth, T0);
    float c1 = fmaf(A1, depth, T1);
    float c2 = fmaf(A2, depth, T2);
    float invz = __fdividef(1.f, c2 + EPSV);
    float u = c0 * invz;
    float v = c1 * invz;
    bool inb = (lane < 16) && (u >= 2.f) && (u <= (float)(WW - 2)) &&
               (v >= 2.f) && (v <= (float)(HH - 2));
    unsigned inmask = __ballot_sync(0xffffffffu, inb);
    float xf = floorf(u), yf = floorf(v);
    // packed bilinear weights {wx, wy} as half2 (one shuffle broadcasts both)
    __half2 wpack_h = __floats2half2_rn(u - xf, v - yf);
    int wpack = *reinterpret_cast<int*>(&wpack_h);
    int offg = ((gf * HH + (int)yf) * WW + (int)xf) * (CC / 2);

    const __half2* lkb = g_lkT + (size_t)b * FF * NPIX * (CC / 2);

    float s[ND];  // per-lane, per-depth accumulators (f merged)

#pragma unroll
    for (int j = 0; j < ND; j++) {
        float sj = 0.f;
#pragma unroll
        for (int f = 0; f < FF; f++) {
            int src = 2 * j + f;
            if (inmask & (1u << src)) {  // warp-uniform
                int off = __shfl_sync(0xffffffffu, offg, src);
                int wp = __shfl_sync(0xffffffffu, wpack, src);
                __half2 wp2 = *reinterpret_cast<__half2*>(&wp);
                __half2 wx2 = __low2half2(wp2);
                __half2 wy2 = __high2half2(wp2);
                const __half2* lk = lkb + off;
                __half2 v00 = lk[lane];
                __half2 v01 = lk[lane + 32];            // +1 px in x
                __half2 v10 = lk[lane + WW * 32];       // +1 px in y
                __half2 v11 = lk[lane + WW * 32 + 32];
                // lerp-form bilinear in half2
                __half2 i0 = __hfma2(__hsub2(v01, v00), wx2, v00);
                __half2 i1 = __hfma2(__hsub2(v11, v10), wx2, v10);
                __half2 sxy = __hfma2(__hsub2(i1, i0), wy2, i0);
                __half2 ad = __habs2(__hsub2(sxy, cur));
                float2 adf = __half22float2(ad);
                float vf = f ? vf1 : vf0;
                sj = fmaf(vf, adf.x + adf.y, sj);
            }
        }
        s[j] = sj;
    }

    // Batched 8-way warp reduction (select-swap butterfly).
    bool b16 = (lane & 16) != 0;
    bool b8 = (lane & 8) != 0;
    bool b4 = (lane & 4) != 0;
    float w[4];
#pragma unroll
    for (int i = 0; i < 4; i++) {
        float keep = b16 ? s[2 * i + 1] : s[2 * i];
        float send = b16 ? s[2 * i] : s[2 * i + 1];
        w[i] = keep + __shfl_xor_sync(0xffffffffu, send, 16);
    }
    float u2[2];
#pragma unroll
    for (int i = 0; i < 2; i++) {
        float keep = b8 ? w[2 * i + 1] : w[2 * i];
        float send = b8 ? w[2 * i] : w[2 * i + 1];
        u2[i] = keep + __shfl_xor_sync(0xffffffffu, send, 8);
    }
    float r;
    {
        float keep = b4 ? u2[1] : u2[0];
        float send = b4 ? u2[0] : u2[1];
        r = keep + __shfl_xor_sync(0xffffffffu, send, 4);
    }
    r += __shfl_xor_sync(0xffffffffu, r, 2);
    r += __shfl_xor_sync(0xffffffffu, r, 1);

    int didx = ((lane >> 2) & 1) * 4 + ((lane >> 3) & 1) * 2 + ((lane >> 4) & 1);
    if ((lane & 3) == 0) {
        // counts from the warp-uniform in-bounds mask: in-bounds & valid
        // => diff > 0 (continuous random features) matching reference counts
        int c0b = ((inmask >> (2 * didx)) & 1) && (vf0 > 0.f);
        int c1b = ((inmask >> (2 * didx + 1)) & 1) && (vf1 > 0.f);
        float cf = (float)(c0b + c1b);
        outp[(size_t)didx * NPIX] = __fdividef(r * (1.0f / CC), cf + EPSV);
    }
}

// ---------------------------------------------------------------------------
// D-axis fixup: cost==0 -> max over D. One block per (b,y) row.
// ---------------------------------------------------------------------------
__global__ __launch_bounds__(128) void fix_kernel(float* __restrict__ out) {
    int by = blockIdx.x;           // 0 .. BB*HH-1
    int b = by / HH;
    int y = by % HH;
    int x = threadIdx.x;
    if (x >= WW) return;
    float* base = out + ((size_t)b * DD * HH + y) * WW + x;
    float mx = 0.f;
#pragma unroll
    for (int d = 0; d < DD; d++) mx = fmaxf(mx, base[(size_t)d * NPIX]);
#pragma unroll
    for (int d = 0; d < DD; d++) {
        float v = base[(size_t)d * NPIX];
        if (v == 0.f) base[(size_t)d * NPIX] = mx;
    }
}

// ---------------------------------------------------------------------------
extern "C" void kernel_launch(void* const* d_in, const int* in_sizes, int n_in,
                              void* d_out, int out_size) {
    const float* current_feats = (const float*)d_in[0];  // [B,C,H,W]
    const float* lookup_feats = (const float*)d_in[1];   // [B,F,C,H,W]
    const float* poses = (const float*)d_in[2];          // [B,F,4,4]
    const float* K = (const float*)d_in[3];              // [B,4,4]
    const float* invK = (const float*)d_in[4];           // [B,4,4]
    const float* depth_bins = (const float*)d_in[5];     // [D]
    float* out = (float*)d_out;                          // [B,D,H,W]

    const int ntiles = NPIX / 32;  // 104
    transpose_kernel<<<(BB * FF + BB) * ntiles, 256>>>(lookup_feats,
                                                       current_feats, K, poses);

    const int TOTW = BB * DG * HH * WW;  // 79872 warps
    int blocks = (TOTW * 32 + 255) / 256;
    cost_kernel<<<blocks, 256>>>(invK, depth_bins, out);

    fix_kernel<<<BB * HH, 128>>>(out);
}